// round 1
// baseline (speedup 1.0000x reference)
#include <cuda_runtime.h>

#define NROWS 100000
#define DIN   128
#define DH    256
#define DOUT  128
#define KNEI  16
#define EPSBN 1e-5f
#define SLOPE 0.2f

// ---------------- scratch (device globals: no allocation allowed) ----------------
__device__ float g_y1[(size_t)NROWS * DH];   // layer1 raw post-leaky output
__device__ float g_y2[(size_t)NROWS * DH];   // layer2 raw post-leaky output
__device__ float g_W2e[DH * DH];             // folded W2
__device__ float g_b2e[DH];
__device__ float g_W3e[DOUT * DH];           // folded W3
__device__ float g_b3e[DOUT];
__device__ float g_sum1[DH], g_sq1[DH];
__device__ float g_sum2[DH], g_sq2[DH];
__device__ float g_sum3[DOUT], g_sq3[DOUT];
__device__ float g_a3[DOUT], g_c3[DOUT];

// ---------------- packed f32x2 helpers (Blackwell dual fp32 pipe) ----------------
__device__ __forceinline__ unsigned long long pack2(float x) {
    unsigned long long r;
    asm("mov.b64 %0, {%1, %1};" : "=l"(r) : "f"(x));
    return r;
}
__device__ __forceinline__ void fma2(unsigned long long& d, unsigned long long a,
                                     unsigned long long b) {
    asm("fma.rn.f32x2 %0, %1, %2, %0;" : "+l"(d) : "l"(a), "l"(b));
}
__device__ __forceinline__ void unpack2(unsigned long long v, float& lo, float& hi) {
    asm("mov.b64 {%0, %1}, %2;" : "=f"(lo), "=f"(hi) : "l"(v));
}

// ---------------- zero per-launch stats (graph replays must be deterministic) ----
__global__ void zero_stats_kernel() {
    int t = threadIdx.x;  // 256
    g_sum1[t] = 0.f; g_sq1[t] = 0.f;
    g_sum2[t] = 0.f; g_sq2[t] = 0.f;
    if (t < DOUT) { g_sum3[t] = 0.f; g_sq3[t] = 0.f; }
}

// ---------------- GEMM: Y = LeakyReLU(X @ W^T + b), + per-column sum/sumsq -------
// C[m][n] = sum_k X[m][k] * W[n][k].  BM=128, BN=128, BK=16, 256 threads, 8x8/thread.
template <int KD>
__global__ __launch_bounds__(256)
void gemm_leaky_stats(const float* __restrict__ Xext, const float* __restrict__ Wext,
                      const float* __restrict__ bext, float* __restrict__ Yext,
                      int layer, int nrows, int nd) {
    const int BM = 128, BN = 128, BK = 16;
    __shared__ __align__(16) float As[BK][BM];
    __shared__ __align__(16) float Bs[BK][BN];
    __shared__ float s_sum[BN], s_sq[BN];

    const float* X    = (layer == 0) ? Xext : (layer == 1 ? g_y1 : g_y2);
    const float* W    = (layer == 0) ? Wext : (layer == 1 ? g_W2e : g_W3e);
    const float* bias = (layer == 0) ? bext : (layer == 1 ? g_b2e : g_b3e);
    float* Y          = (layer == 2) ? Yext : (layer == 0 ? g_y1 : g_y2);
    float* gsum       = (layer == 0) ? g_sum1 : (layer == 1 ? g_sum2 : g_sum3);
    float* gsq        = (layer == 0) ? g_sq1  : (layer == 1 ? g_sq2  : g_sq3);

    int tid = threadIdx.x;
    int bm0 = blockIdx.x * BM;
    int bn0 = blockIdx.y * BN;
    if (tid < BN) { s_sum[tid] = 0.f; s_sq[tid] = 0.f; }

    int tm = tid >> 4, tn = tid & 15;

    // loader: 128x16 tile = 512 float4; each thread loads float4 ids (tid, tid+256)
    int ar0 = tid >> 2,        ac0 = tid & 3;
    int ar1 = (tid + 256) >> 2, ac1 = (tid + 256) & 3;
    int gra0 = bm0 + ar0, gra1 = bm0 + ar1;
    const float4 z4 = make_float4(0.f, 0.f, 0.f, 0.f);

    float4 pa0, pa1, pb0, pb1;
    pa0 = (gra0 < nrows) ? __ldg((const float4*)(X + (size_t)gra0 * KD + ac0 * 4)) : z4;
    pa1 = (gra1 < nrows) ? __ldg((const float4*)(X + (size_t)gra1 * KD + ac1 * 4)) : z4;
    pb0 = __ldg((const float4*)(W + (size_t)(bn0 + ar0) * KD + ac0 * 4));
    pb1 = __ldg((const float4*)(W + (size_t)(bn0 + ar1) * KD + ac1 * 4));

    unsigned long long acc[8][4];
#pragma unroll
    for (int i = 0; i < 8; i++)
#pragma unroll
        for (int j = 0; j < 4; j++) acc[i][j] = 0ull;

    const int nk = KD / BK;
    for (int kb = 0; kb < nk; kb++) {
        __syncthreads();
        As[ac0 * 4 + 0][ar0] = pa0.x; As[ac0 * 4 + 1][ar0] = pa0.y;
        As[ac0 * 4 + 2][ar0] = pa0.z; As[ac0 * 4 + 3][ar0] = pa0.w;
        As[ac1 * 4 + 0][ar1] = pa1.x; As[ac1 * 4 + 1][ar1] = pa1.y;
        As[ac1 * 4 + 2][ar1] = pa1.z; As[ac1 * 4 + 3][ar1] = pa1.w;
        Bs[ac0 * 4 + 0][ar0] = pb0.x; Bs[ac0 * 4 + 1][ar0] = pb0.y;
        Bs[ac0 * 4 + 2][ar0] = pb0.z; Bs[ac0 * 4 + 3][ar0] = pb0.w;
        Bs[ac1 * 4 + 0][ar1] = pb1.x; Bs[ac1 * 4 + 1][ar1] = pb1.y;
        Bs[ac1 * 4 + 2][ar1] = pb1.z; Bs[ac1 * 4 + 3][ar1] = pb1.w;
        __syncthreads();

        if (kb + 1 < nk) {  // prefetch next tile (LDG overlapped with compute)
            int kc = (kb + 1) * BK;
            pa0 = (gra0 < nrows) ? __ldg((const float4*)(X + (size_t)gra0 * KD + kc + ac0 * 4)) : z4;
            pa1 = (gra1 < nrows) ? __ldg((const float4*)(X + (size_t)gra1 * KD + kc + ac1 * 4)) : z4;
            pb0 = __ldg((const float4*)(W + (size_t)(bn0 + ar0) * KD + kc + ac0 * 4));
            pb1 = __ldg((const float4*)(W + (size_t)(bn0 + ar1) * KD + kc + ac1 * 4));
        }

#pragma unroll
        for (int kk = 0; kk < BK; kk++) {
            float4 av0 = *(const float4*)&As[kk][tm * 8];
            float4 av1 = *(const float4*)&As[kk][tm * 8 + 4];
            ulonglong2 bb0 = *(const ulonglong2*)&Bs[kk][tn * 8];
            ulonglong2 bb1 = *(const ulonglong2*)&Bs[kk][tn * 8 + 4];
            float a_[8] = {av0.x, av0.y, av0.z, av0.w, av1.x, av1.y, av1.z, av1.w};
            unsigned long long bq[4] = {bb0.x, bb0.y, bb1.x, bb1.y};
#pragma unroll
            for (int i = 0; i < 8; i++) {
                unsigned long long ap = pack2(a_[i]);
                fma2(acc[i][0], ap, bq[0]);
                fma2(acc[i][1], ap, bq[1]);
                fma2(acc[i][2], ap, bq[2]);
                fma2(acc[i][3], ap, bq[3]);
            }
        }
    }

    // epilogue: bias + LeakyReLU + store + per-column stats
    float bvals[8];
#pragma unroll
    for (int j = 0; j < 8; j++) bvals[j] = __ldg(bias + bn0 + tn * 8 + j);

    float csum[8], csq[8];
#pragma unroll
    for (int j = 0; j < 8; j++) { csum[j] = 0.f; csq[j] = 0.f; }

#pragma unroll
    for (int i = 0; i < 8; i++) {
        int gr = bm0 + tm * 8 + i;
        bool valid = gr < nrows;
        float out[8];
#pragma unroll
        for (int jp = 0; jp < 4; jp++) {
            float lo, hi;
            unpack2(acc[i][jp], lo, hi);
            float v0 = lo + bvals[jp * 2];
            float v1 = hi + bvals[jp * 2 + 1];
            v0 = v0 > 0.f ? v0 : SLOPE * v0;
            v1 = v1 > 0.f ? v1 : SLOPE * v1;
            out[jp * 2] = v0; out[jp * 2 + 1] = v1;
        }
        if (valid) {
            *(float4*)(Y + (size_t)gr * nd + bn0 + tn * 8)     = make_float4(out[0], out[1], out[2], out[3]);
            *(float4*)(Y + (size_t)gr * nd + bn0 + tn * 8 + 4) = make_float4(out[4], out[5], out[6], out[7]);
#pragma unroll
            for (int j = 0; j < 8; j++) { csum[j] += out[j]; csq[j] += out[j] * out[j]; }
        }
    }
#pragma unroll
    for (int j = 0; j < 8; j++) {
        atomicAdd(&s_sum[tn * 8 + j], csum[j]);
        atomicAdd(&s_sq[tn * 8 + j], csq[j]);
    }
    __syncthreads();
    if (tid < BN) {
        atomicAdd(&gsum[bn0 + tid], s_sum[tid]);
        atomicAdd(&gsq[bn0 + tid], s_sq[tid]);
    }
}

// ---- fold BN affine of previous layer into next layer's weights -----------------
// layer==1: stats1 -> (W2,b2) => g_W2e,g_b2e ; layer==2: stats2 -> (W3,b3) => g_W3e,g_b3e
__global__ void fold_kernel(const float* __restrict__ W, const float* __restrict__ b,
                            const float* __restrict__ g, const float* __restrict__ beta,
                            int layer) {
    int j = threadIdx.x;   // 256 = KD
    int o = blockIdx.x;    // output row
    const float* sum = (layer == 1) ? g_sum1 : g_sum2;
    const float* sq  = (layer == 1) ? g_sq1  : g_sq2;
    float* We        = (layer == 1) ? g_W2e  : g_W3e;
    float* be        = (layer == 1) ? g_b2e  : g_b3e;

    const float invN = 1.0f / (float)NROWS;
    float mean = sum[j] * invN;
    float var  = sq[j] * invN - mean * mean;
    float a = g[j] * rsqrtf(var + EPSBN);
    float c = beta[j] - mean * a;
    float w = W[o * DH + j];
    We[o * DH + j] = w * a;

    __shared__ float red[DH];
    red[j] = w * c;
    __syncthreads();
    for (int s = DH / 2; s > 0; s >>= 1) {
        if (j < s) red[j] += red[j + s];
        __syncthreads();
    }
    if (j == 0) be[o] = b[o] + red[0];
}

// ---- layer-3 BN affine coefficients ---------------------------------------------
__global__ void prep3_kernel(const float* __restrict__ g, const float* __restrict__ beta) {
    int j = threadIdx.x;  // 128
    const float invN = 1.0f / (float)NROWS;
    float mean = g_sum3[j] * invN;
    float var  = g_sq3[j] * invN - mean * mean;
    float a = g[j] * rsqrtf(var + EPSBN);
    g_a3[j] = a;
    g_c3[j] = beta[j] - mean * a;
}

// ---- in-place affine: y3 -> f = y3*a3 + c3 (f region of d_out) ------------------
__global__ void affine_kernel(float* __restrict__ f) {
    long long idx = (long long)blockIdx.x * blockDim.x + threadIdx.x;
    if (idx * 4 >= (long long)NROWS * DOUT) return;
    float4 v = *(float4*)(f + idx * 4);
    int j = (int)((idx * 4) & (DOUT - 1));
    v.x = v.x * g_a3[j]     + g_c3[j];
    v.y = v.y * g_a3[j + 1] + g_c3[j + 1];
    v.z = v.z * g_a3[j + 2] + g_c3[j + 2];
    v.w = v.w * g_a3[j + 3] + g_c3[j + 3];
    *(float4*)(f + idx * 4) = v;
}

// ---- neighbor-mean gather: node_update[i] = mean_k f[nidx[i*K+k]] ---------------
__global__ void gather_kernel(const int* __restrict__ nidx, const float* __restrict__ f,
                              float* __restrict__ out) {
    __shared__ int sidx[2 * KNEI];
    int tid = threadIdx.x;              // 256 threads = 2 nodes
    int node0 = blockIdx.x * 2;
    if (tid < 2 * KNEI) sidx[tid] = nidx[(size_t)node0 * KNEI + tid];
    __syncthreads();
    int local = tid >> 7;               // 0 or 1
    int j = tid & (DOUT - 1);
    float s = 0.f;
#pragma unroll
    for (int k = 0; k < KNEI; k++) {
        int nk = sidx[local * KNEI + k];
        s += __ldg(f + (size_t)nk * DOUT + j);
    }
    out[(size_t)(node0 + local) * DOUT + j] = s * (1.0f / KNEI);
}

// ---------------------------------------------------------------------------------
extern "C" void kernel_launch(void* const* d_in, const int* in_sizes, int n_in,
                              void* d_out, int out_size) {
    const float* X   = (const float*)d_in[0];
    const int*   nid = (const int*)d_in[1];
    // d_in[2] = prob_retained (unused by reference)
    const float* W1  = (const float*)d_in[3];
    const float* b1  = (const float*)d_in[4];
    const float* g1  = (const float*)d_in[5];
    const float* be1 = (const float*)d_in[6];
    const float* W2  = (const float*)d_in[7];
    const float* b2  = (const float*)d_in[8];
    const float* g2  = (const float*)d_in[9];
    const float* be2 = (const float*)d_in[10];
    const float* W3  = (const float*)d_in[11];
    const float* b3  = (const float*)d_in[12];
    const float* g3  = (const float*)d_in[13];
    const float* be3 = (const float*)d_in[14];

    float* out  = (float*)d_out;                       // node_update [N, DOUT]
    float* fbuf = out + (size_t)NROWS * DOUT;          // f           [N, DOUT]

    const int mblocks = (NROWS + 127) / 128;           // 782

    zero_stats_kernel<<<1, 256>>>();

    // layer 1: X[N,128] @ W1^T -> g_y1[N,256]   (+stats1)
    gemm_leaky_stats<DIN><<<dim3(mblocks, DH / 128), 256>>>(X, W1, b1, nullptr, 0, NROWS, DH);
    // fold BN1 into (W2, b2)
    fold_kernel<<<DH, DH>>>(W2, b2, g1, be1, 1);
    // layer 2: g_y1 @ W2e^T -> g_y2[N,256]      (+stats2)
    gemm_leaky_stats<DH><<<dim3(mblocks, DH / 128), 256>>>(nullptr, nullptr, nullptr, nullptr, 1, NROWS, DH);
    // fold BN2 into (W3, b3)
    fold_kernel<<<DOUT, DH>>>(W3, b3, g2, be2, 2);
    // layer 3: g_y2 @ W3e^T -> fbuf[N,128] (raw y3, +stats3)
    gemm_leaky_stats<DH><<<dim3(mblocks, DOUT / 128), 256>>>(nullptr, nullptr, nullptr, fbuf, 2, NROWS, DOUT);
    // BN3 affine coefficients, apply in place: fbuf = f
    prep3_kernel<<<1, DOUT>>>(g3, be3);
    affine_kernel<<<(NROWS * DOUT / 4 + 255) / 256, 256>>>(fbuf);
    // neighbor mean (mean of affine == affine of mean; fbuf already == f)
    gather_kernel<<<NROWS / 2, 256>>>(nid, fbuf, out);
}

// round 5
// speedup vs baseline: 2.0259x; 2.0259x over previous
#include <cuda_runtime.h>
#include <cuda_bf16.h>
#include <cstdint>

#define NROWS 100000
#define DIN   128
#define DH    256
#define DOUT  128
#define KNEI  16
#define EPSBN 1e-5f
#define SLOPE 0.2f

// ---------------- device scratch (no allocations allowed) ------------------------
__device__ float g_y1[(size_t)NROWS * DH];   // layer1 out fp32
__device__ float g_y2[(size_t)NROWS * DH];   // layer2 out fp32
__device__ float g_W2e[DH * DH];             // folded W2 (fp32, as in passing R1)
__device__ float g_b2e[DH];
__device__ float g_W3e[DOUT * DH];           // folded W3 (fp32)
__device__ float g_b3e[DOUT];
__device__ float g_sum1[DH], g_sq1[DH];
__device__ float g_sum2[DH], g_sq2[DH];
__device__ float g_sum3[DOUT], g_sq3[DOUT];
__device__ float g_a3[DOUT], g_c3[DOUT];

// ---------------- helpers ---------------------------------------------------------
__device__ __forceinline__ uint32_t smem_u32(const void* p) {
    uint32_t a;
    asm("{ .reg .u64 t; cvta.to.shared.u64 t, %1; cvt.u32.u64 %0, t; }" : "=r"(a) : "l"(p));
    return a;
}
__device__ __forceinline__ uint32_t lds32(uint32_t a) {
    uint32_t v;
    asm volatile("ld.shared.b32 %0, [%1];" : "=r"(v) : "r"(a));
    return v;
}
__device__ __forceinline__ void mma16816(float* c, const uint32_t* a, const uint32_t* b) {
    asm volatile("mma.sync.aligned.m16n8k16.row.col.f32.bf16.bf16.f32 "
                 "{%0,%1,%2,%3}, {%4,%5,%6,%7}, {%8,%9}, {%0,%1,%2,%3};"
                 : "+f"(c[0]), "+f"(c[1]), "+f"(c[2]), "+f"(c[3])
                 : "r"(a[0]), "r"(a[1]), "r"(a[2]), "r"(a[3]), "r"(b[0]), "r"(b[1]));
}
__device__ __forceinline__ uint32_t pack_bf2(float x, float y) {
    __nv_bfloat16 a = __float2bfloat16(x), b = __float2bfloat16(y);
    return (uint32_t)__bfloat16_as_ushort(a) | ((uint32_t)__bfloat16_as_ushort(b) << 16);
}
__device__ __forceinline__ void split2(float x, float y, uint32_t& hw, uint32_t& lw) {
    __nv_bfloat16 a = __float2bfloat16(x), b = __float2bfloat16(y);
    hw = (uint32_t)__bfloat16_as_ushort(a) | ((uint32_t)__bfloat16_as_ushort(b) << 16);
    lw = pack_bf2(x - __bfloat162float(a), y - __bfloat162float(b));
}

// ---------------- smem geometry (natural padded layout) --------------------------
// BM=128, BN=64, BK=32 bf16.  Row stride 80 bytes: fragment reads conflict-free.
#define ARS   80
#define OAH   0
#define OAL   10240
#define OBH   20480
#define OBL   25600
#define SMTOT (30720 + 768)

// ---------------- tile loaders (all fp32 sources, split inline) ------------------
template <int KD>
__device__ __forceinline__ void ldgA(float4 v[8], const float* __restrict__ A,
                                     int bm0, int kb, int tid) {
    int r = tid >> 1;
    int cb = kb * 32 + (tid & 1) * 4;
#pragma unroll
    for (int h = 0; h < 2; h++) {
        int gr = bm0 + r + h * 64;
        const float* p = A + (size_t)gr * KD + cb;
        bool ok = gr < NROWS;
#pragma unroll
        for (int i = 0; i < 4; i++)
            v[h * 4 + i] = ok ? __ldg((const float4*)(p + i * 8)) : make_float4(0.f, 0.f, 0.f, 0.f);
    }
}

__device__ __forceinline__ void stsA(char* aH, char* aL, const float4 v[8], int tid) {
    int e = (tid & 1) * 8;
#pragma unroll
    for (int h = 0; h < 2; h++) {
        int r = (tid >> 1) + h * 64;
#pragma unroll
        for (int i = 0; i < 4; i++) {
            float4 f = v[h * 4 + i];
            uint32_t h0, l0, h1, l1;
            split2(f.x, f.y, h0, l0);
            split2(f.z, f.w, h1, l1);
            int off = r * ARS + i * 16 + e;
            *(uint2*)(aH + off) = make_uint2(h0, h1);
            *(uint2*)(aL + off) = make_uint2(l0, l1);
        }
    }
}

template <int KD>
__device__ __forceinline__ void ldgB(float4 v[4], const float* __restrict__ W,
                                     int bn0, int kb, int tid) {
    int r = tid >> 1;
    const float* p = W + (size_t)(bn0 + r) * KD + kb * 32 + (tid & 1) * 16;
#pragma unroll
    for (int i = 0; i < 4; i++) v[i] = __ldg((const float4*)(p + i * 4));
}

__device__ __forceinline__ void stsB(char* bH, char* bL, const float4 v[4], int tid) {
    int r = tid >> 1;
    int base = r * ARS + (tid & 1) * 32;
#pragma unroll
    for (int i = 0; i < 4; i++) {
        float4 f = v[i];
        uint32_t h0, l0, h1, l1;
        split2(f.x, f.y, h0, l0);
        split2(f.z, f.w, h1, l1);
        int off = base + i * 8;
        *(uint2*)(bH + off) = make_uint2(h0, h1);
        *(uint2*)(bL + off) = make_uint2(l0, l1);
    }
}

// ---------------- compute one BK=32 stage (plain-LDS fragments, bf16x3) ----------
__device__ __forceinline__ void computeStage(uint32_t sAh, uint32_t sAl,
                                             uint32_t sBh, uint32_t sBl,
                                             float acc[4][4][4], int wid, int lane) {
    const int mbase = (wid >> 1) * 64;
    const int nbase = (wid & 1) * 32;
    const int g = lane >> 2, t = lane & 3;
#pragma unroll
    for (int ks = 0; ks < 2; ks++) {
        const uint32_t koff = (uint32_t)ks * 32 + t * 4;
        uint32_t bh[4][2], bl[4][2];
#pragma unroll
        for (int nt = 0; nt < 4; nt++) {
            uint32_t off = (uint32_t)(nbase + nt * 8 + g) * ARS + koff;
            bh[nt][0] = lds32(sBh + off);
            bh[nt][1] = lds32(sBh + off + 16);
            bl[nt][0] = lds32(sBl + off);
            bl[nt][1] = lds32(sBl + off + 16);
        }
#pragma unroll
        for (int mt = 0; mt < 4; mt++) {
            uint32_t aoff = (uint32_t)(mbase + mt * 16 + g) * ARS + koff;
            uint32_t ah[4], al[4];
            ah[0] = lds32(sAh + aoff);
            ah[1] = lds32(sAh + aoff + 8 * ARS);
            ah[2] = lds32(sAh + aoff + 16);
            ah[3] = lds32(sAh + aoff + 8 * ARS + 16);
            al[0] = lds32(sAl + aoff);
            al[1] = lds32(sAl + aoff + 8 * ARS);
            al[2] = lds32(sAl + aoff + 16);
            al[3] = lds32(sAl + aoff + 8 * ARS + 16);
#pragma unroll
            for (int nt = 0; nt < 4; nt++) {
                mma16816(acc[mt][nt], ah, bh[nt]);
                mma16816(acc[mt][nt], al, bh[nt]);
                mma16816(acc[mt][nt], ah, bl[nt]);
            }
        }
    }
}

// ---------------- GEMM kernel: Y = LeakyReLU(A @ W^T + bias), + col stats --------
template <int KD, int NO, int MODE>
__global__ void __launch_bounds__(128, 3)
gemm_mma3(const float* __restrict__ Xext, const float* __restrict__ bext,
          float* __restrict__ Yext) {
    extern __shared__ char smem[];
    constexpr int NKB = KD / 32;
    const int tid = threadIdx.x, wid = tid >> 5, lane = tid & 31;
    const int bm0 = blockIdx.x * 128, bn0 = blockIdx.y * 64;
    const uint32_t sb = smem_u32(smem);

    const float* A = (MODE == 0) ? Xext : (MODE == 1 ? g_y1 : g_y2);
    const float* W = (MODE == 0) ? (Xext ? Xext + 0 : nullptr) : nullptr;  // placeholder
    const float* Wp = (MODE == 0) ? nullptr : (MODE == 1 ? g_W2e : g_W3e);
    // MODE 0 weight comes through bext? no — pass W1 via Yext trick is ugly; use globals:
    // For MODE 0 we pass W1 as 'Wext' through the unused half of Xext? Keep it simple:
    // we smuggle W1 via a __device__ pointer set below is not allowed in graphs.
    // Instead: MODE 0 uses Wext = bext? NO. -> We add a 4th param-free solution:
    (void)W;
    const float* bias = (MODE == 0) ? bext : (MODE == 1 ? g_b2e : g_b3e);
    float* Y    = (MODE == 0) ? g_y1 : (MODE == 1 ? g_y2 : Yext);
    float* gsum = (MODE == 0) ? g_sum1 : (MODE == 1 ? g_sum2 : g_sum3);
    float* gsq  = (MODE == 0) ? g_sq1  : (MODE == 1 ? g_sq2  : g_sq3);
    // For MODE 0, Yext carries W1 (it is unused as an output there).
    const float* Wsel = (MODE == 0) ? Yext : Wp;

    float* s_bias = (float*)(smem + 30720);
    float* s_sum  = s_bias + 64;
    float* s_sq   = s_sum + 64;
    if (tid < 64) { s_bias[tid] = __ldg(bias + bn0 + tid); s_sum[tid] = 0.f; s_sq[tid] = 0.f; }

    float acc[4][4][4];
#pragma unroll
    for (int i = 0; i < 4; i++)
#pragma unroll
        for (int j = 0; j < 4; j++)
#pragma unroll
            for (int k = 0; k < 4; k++) acc[i][j][k] = 0.f;

    float4 va[8], vb[4];
    ldgA<KD>(va, A, bm0, 0, tid);
    ldgB<KD>(vb, Wsel, bn0, 0, tid);

    for (int kb = 0; kb < NKB; kb++) {
        __syncthreads();
        stsA(smem + OAH, smem + OAL, va, tid);
        stsB(smem + OBH, smem + OBL, vb, tid);
        __syncthreads();
        if (kb + 1 < NKB) {
            ldgA<KD>(va, A, bm0, kb + 1, tid);
            ldgB<KD>(vb, Wsel, bn0, kb + 1, tid);
        }
        computeStage(sb + OAH, sb + OAL, sb + OBH, sb + OBL, acc, wid, lane);
    }

    // epilogue: bias + leaky + store + stats
    const int wm = (wid >> 1) * 64, wn = (wid & 1) * 32;
    float csum[4][2], csq[4][2];
#pragma unroll
    for (int nt = 0; nt < 4; nt++) { csum[nt][0] = csum[nt][1] = 0.f; csq[nt][0] = csq[nt][1] = 0.f; }

#pragma unroll
    for (int mt = 0; mt < 4; mt++) {
        int r0 = bm0 + wm + mt * 16 + (lane >> 2);
        int r1 = r0 + 8;
#pragma unroll
        for (int nt = 0; nt < 4; nt++) {
            int jl = wn + nt * 8 + (lane & 3) * 2;
            float b0 = s_bias[jl], b1 = s_bias[jl + 1];
            float x0 = acc[mt][nt][0] + b0; x0 = x0 > 0.f ? x0 : SLOPE * x0;
            float x1 = acc[mt][nt][1] + b1; x1 = x1 > 0.f ? x1 : SLOPE * x1;
            float x2 = acc[mt][nt][2] + b0; x2 = x2 > 0.f ? x2 : SLOPE * x2;
            float x3 = acc[mt][nt][3] + b1; x3 = x3 > 0.f ? x3 : SLOPE * x3;
            if (r0 < NROWS) {
                *(float2*)(Y + (size_t)r0 * NO + bn0 + jl) = make_float2(x0, x1);
                csum[nt][0] += x0; csum[nt][1] += x1;
                csq[nt][0] += x0 * x0; csq[nt][1] += x1 * x1;
            }
            if (r1 < NROWS) {
                *(float2*)(Y + (size_t)r1 * NO + bn0 + jl) = make_float2(x2, x3);
                csum[nt][0] += x2; csum[nt][1] += x3;
                csq[nt][0] += x2 * x2; csq[nt][1] += x3 * x3;
            }
        }
    }
#pragma unroll
    for (int nt = 0; nt < 4; nt++)
#pragma unroll
        for (int p = 0; p < 2; p++) {
            float s = csum[nt][p], q = csq[nt][p];
            s += __shfl_xor_sync(0xFFFFFFFFu, s, 4);  q += __shfl_xor_sync(0xFFFFFFFFu, q, 4);
            s += __shfl_xor_sync(0xFFFFFFFFu, s, 8);  q += __shfl_xor_sync(0xFFFFFFFFu, q, 8);
            s += __shfl_xor_sync(0xFFFFFFFFu, s, 16); q += __shfl_xor_sync(0xFFFFFFFFu, q, 16);
            if (lane < 4) {
                int col = wn + nt * 8 + lane * 2 + p;
                atomicAdd(&s_sum[col], s);
                atomicAdd(&s_sq[col], q);
            }
        }
    __syncthreads();
    if (tid < 64) {
        atomicAdd(gsum + bn0 + tid, s_sum[tid]);
        atomicAdd(gsq + bn0 + tid, s_sq[tid]);
    }
}

// ---------------- R1-verbatim small kernels --------------------------------------
__global__ void zero_stats_kernel() {
    int t = threadIdx.x;  // 256
    g_sum1[t] = 0.f; g_sq1[t] = 0.f;
    g_sum2[t] = 0.f; g_sq2[t] = 0.f;
    if (t < DOUT) { g_sum3[t] = 0.f; g_sq3[t] = 0.f; }
}

__global__ void fold_kernel(const float* __restrict__ W, const float* __restrict__ b,
                            const float* __restrict__ g, const float* __restrict__ beta,
                            int layer) {
    int j = threadIdx.x;   // 256 = DH
    int o = blockIdx.x;
    const float* sum = (layer == 1) ? g_sum1 : g_sum2;
    const float* sq  = (layer == 1) ? g_sq1  : g_sq2;
    float* We        = (layer == 1) ? g_W2e  : g_W3e;
    float* be        = (layer == 1) ? g_b2e  : g_b3e;

    const float invN = 1.0f / (float)NROWS;
    float mean = sum[j] * invN;
    float var  = sq[j] * invN - mean * mean;
    float a = g[j] * rsqrtf(var + EPSBN);
    float c = beta[j] - mean * a;
    float w = W[o * DH + j];
    We[o * DH + j] = w * a;

    __shared__ float red[DH];
    red[j] = w * c;
    __syncthreads();
    for (int s = DH / 2; s > 0; s >>= 1) {
        if (j < s) red[j] += red[j + s];
        __syncthreads();
    }
    if (j == 0) be[o] = b[o] + red[0];
}

__global__ void prep3_kernel(const float* __restrict__ g, const float* __restrict__ beta) {
    int j = threadIdx.x;  // 128
    const float invN = 1.0f / (float)NROWS;
    float mean = g_sum3[j] * invN;
    float var  = g_sq3[j] * invN - mean * mean;
    float a = g[j] * rsqrtf(var + EPSBN);
    g_a3[j] = a;
    g_c3[j] = beta[j] - mean * a;
}

__global__ void affine_kernel(float* __restrict__ f) {
    long long idx = (long long)blockIdx.x * blockDim.x + threadIdx.x;
    if (idx * 4 >= (long long)NROWS * DOUT) return;
    float4 v = *(float4*)(f + idx * 4);
    int j = (int)((idx * 4) & (DOUT - 1));
    v.x = v.x * g_a3[j]     + g_c3[j];
    v.y = v.y * g_a3[j + 1] + g_c3[j + 1];
    v.z = v.z * g_a3[j + 2] + g_c3[j + 2];
    v.w = v.w * g_a3[j + 3] + g_c3[j + 3];
    *(float4*)(f + idx * 4) = v;
}

__global__ void gather_kernel(const int* __restrict__ nidx, const float* __restrict__ f,
                              float* __restrict__ out) {
    __shared__ int sidx[2 * KNEI];
    int tid = threadIdx.x;              // 256 threads = 2 nodes
    int node0 = blockIdx.x * 2;
    if (tid < 2 * KNEI) sidx[tid] = nidx[(size_t)node0 * KNEI + tid];
    __syncthreads();
    int local = tid >> 7;
    int j = tid & (DOUT - 1);
    float s = 0.f;
#pragma unroll
    for (int k = 0; k < KNEI; k++) {
        int nk = sidx[local * KNEI + k];
        s += __ldg(f + (size_t)nk * DOUT + j);
    }
    out[(size_t)(node0 + local) * DOUT + j] = s * (1.0f / KNEI);
}

// ---------------------------------------------------------------------------------
extern "C" void kernel_launch(void* const* d_in, const int* in_sizes, int n_in,
                              void* d_out, int out_size) {
    const float* X   = (const float*)d_in[0];
    const int*   nid = (const int*)d_in[1];
    const float* W1  = (const float*)d_in[3];
    const float* b1  = (const float*)d_in[4];
    const float* g1  = (const float*)d_in[5];
    const float* be1 = (const float*)d_in[6];
    const float* W2  = (const float*)d_in[7];
    const float* b2  = (const float*)d_in[8];
    const float* g2  = (const float*)d_in[9];
    const float* be2 = (const float*)d_in[10];
    const float* W3  = (const float*)d_in[11];
    const float* b3  = (const float*)d_in[12];
    const float* g3  = (const float*)d_in[13];
    const float* be3 = (const float*)d_in[14];

    float* out  = (float*)d_out;                   // node_update [N, DOUT]
    float* fbuf = out + (size_t)NROWS * DOUT;      // f           [N, DOUT]

    const int mblocks = (NROWS + 127) / 128;       // 782

    cudaFuncSetAttribute(gemm_mma3<128, 256, 0>, cudaFuncAttributeMaxDynamicSharedMemorySize, SMTOT);
    cudaFuncSetAttribute(gemm_mma3<256, 256, 1>, cudaFuncAttributeMaxDynamicSharedMemorySize, SMTOT);
    cudaFuncSetAttribute(gemm_mma3<256, 128, 2>, cudaFuncAttributeMaxDynamicSharedMemorySize, SMTOT);

    zero_stats_kernel<<<1, 256>>>();

    // layer 1: X @ W1^T -> g_y1 (+stats1).  W1 passed via 3rd arg (unused as output in MODE 0)
    gemm_mma3<128, 256, 0><<<dim3(mblocks, 4), 128, SMTOT>>>(X, b1, (float*)W1);
    fold_kernel<<<DH, DH>>>(W2, b2, g1, be1, 1);
    gemm_mma3<256, 256, 1><<<dim3(mblocks, 4), 128, SMTOT>>>(nullptr, nullptr, nullptr);
    fold_kernel<<<DOUT, DH>>>(W3, b3, g2, be2, 2);
    // layer 3: g_y2 @ W3e^T -> fbuf (raw y3, +stats3)
    gemm_mma3<256, 128, 2><<<dim3(mblocks, 2), 128, SMTOT>>>(nullptr, nullptr, fbuf);

    prep3_kernel<<<1, DOUT>>>(g3, be3);
    affine_kernel<<<(NROWS * DOUT / 4 + 255) / 256, 256>>>(fbuf);
    gather_kernel<<<NROWS / 2, 256>>>(nid, fbuf, out);
}